// round 1
// baseline (speedup 1.0000x reference)
#include <cuda_runtime.h>
#include <math.h>

#define MESHN 128
#define M2    16384
#define M3    2097152

// Scratch (statically allocated device globals — no runtime allocation)
__device__ float  g_real[M3];
__device__ float2 g_A[M3];
__device__ float2 g_B[M3];
__device__ float2 g_C[M3];

// ---------------------------------------------------------------------------
__global__ void zero_kernel(float* __restrict__ r) {
    int i = blockIdx.x * 256 + threadIdx.x;
    r[i] = 0.0f;
}

// ---------------------------------------------------------------------------
__global__ void paint_kernel(const float* __restrict__ pos,
                             float* __restrict__ grid, int N) {
    int n = blockIdx.x * 256 + threadIdx.x;
    if (n >= N) return;
    float px = pos[3*n+0], py = pos[3*n+1], pz = pos[3*n+2];
    float f0x = floorf(px), f0y = floorf(py), f0z = floorf(pz);
    int ix = ((int)f0x) & 127, iy = ((int)f0y) & 127, iz = ((int)f0z) & 127;
    float dx = px - f0x, dy = py - f0y, dz = pz - f0z;
    float wx[2] = {1.0f - dx, dx};
    float wy[2] = {1.0f - dy, dy};
    float wz[2] = {1.0f - dz, dz};
    int xi[2] = {ix, (ix + 1) & 127};
    int yi[2] = {iy, (iy + 1) & 127};
    int zi[2] = {iz, (iz + 1) & 127};
#pragma unroll
    for (int a = 0; a < 2; a++)
#pragma unroll
        for (int b = 0; b < 2; b++)
#pragma unroll
            for (int c = 0; c < 2; c++)
                atomicAdd(&grid[xi[a]*M2 + yi[b]*MESHN + zi[c]],
                          wx[a]*wy[b]*wz[c]);
}

// ---------------------------------------------------------------------------
// One 1D-FFT pass along one axis. 16 lines (128 complex pts each) per block,
// 256 threads. Stockham radix-2, 7 stages, shared-memory ping-pong, shared
// twiddle table (exp(sign*2*pi*i*k/128), k in [0,64)).
//   element address = base + l*LSTRIDE + i*ISTRIDE
//   base = blockIdx.y*M2 + blockIdx.x*XBS
template<int ISTRIDE, int LSTRIDE, int XBS, bool INV, bool REAL_IN>
__global__ void __launch_bounds__(256)
fft_pass(const float2* __restrict__ in, const float* __restrict__ rin,
         float2* __restrict__ out) {
    __shared__ float2 sA[2048];
    __shared__ float2 sB[2048];
    __shared__ float2 tw[64];

    int tid = threadIdx.x;
    if (tid < 64) {
        float ang = (INV ? 1.0f : -1.0f) * 6.283185307179586f * (float)tid * (1.0f/128.0f);
        float s, c;
        sincosf(ang, &s, &c);
        tw[tid] = make_float2(c, s);
    }

    int base = blockIdx.y * M2 + blockIdx.x * XBS;

    // load 16 lines (coalesced per-axis mapping)
#pragma unroll
    for (int k = 0; k < 8; k++) {
        int e = tid + k * 256;
        int l, i;
        if (ISTRIDE == 1) { l = e >> 7; i = e & 127; }
        else              { i = e >> 4; l = e & 15;  }
        int g = base + l * LSTRIDE + i * ISTRIDE;
        float2 v;
        if (REAL_IN) v = make_float2(rin[g], 0.0f);
        else         v = in[g];
        sA[l * 128 + i] = v;
    }
    __syncthreads();

    float2* src = sA;
    float2* dst = sB;
#pragma unroll
    for (int stage = 0; stage < 7; stage++) {
        int s = 1 << stage;
#pragma unroll
        for (int w0 = 0; w0 < 4; w0++) {
            int w    = tid + w0 * 256;
            int line = w >> 6;
            int j    = w & 63;
            int q    = j & (s - 1);
            int t    = j ^ q;              // = p*s, twiddle table index
            float2 a = src[line * 128 + j];
            float2 b = src[line * 128 + j + 64];
            float2 W = tw[t];
            float2 apb = make_float2(a.x + b.x, a.y + b.y);
            float2 amb = make_float2(a.x - b.x, a.y - b.y);
            float2 bt  = make_float2(amb.x * W.x - amb.y * W.y,
                                     amb.x * W.y + amb.y * W.x);
            int d0 = 2 * (j - q) + q;      // q + 2*s*p
            dst[line * 128 + d0]     = apb;
            dst[line * 128 + d0 + s] = bt;
        }
        __syncthreads();
        float2* tmp = src; src = dst; dst = tmp;
    }

    // store (result is in src after final swap)
#pragma unroll
    for (int k = 0; k < 8; k++) {
        int e = tid + k * 256;
        int l, i;
        if (ISTRIDE == 1) { l = e >> 7; i = e & 127; }
        else              { i = e >> 4; l = e & 15;  }
        out[base + l * LSTRIDE + i * ISTRIDE] = src[l * 128 + i];
    }
}

// ---------------------------------------------------------------------------
// Spectral op: pot_k = delta_k * (-1/kk) * exp(-kl2/kk) * exp(-kk^2) / M3
//   Bxy = pot * (ky - i*kx)   (= Fx_k + i*Fy_k)
//   Cz  = pot * (-i*kz)       (= Fz_k)
__global__ void filter_kernel(const float2* __restrict__ A,
                              float2* __restrict__ Bxy,
                              float2* __restrict__ Cz) {
    int idx = blockIdx.x * 256 + threadIdx.x;
    int z = idx & 127, y = (idx >> 7) & 127, x = idx >> 14;
    const float kunit = 6.283185307179586f / 128.0f;
    float kx = (float)((x < 64) ? x : x - 128) * kunit;
    float ky = (float)((y < 64) ? y : y - 128) * kunit;
    float kz = (float)((z < 64) ? z : z - 128) * kunit;
    float kk = kx*kx + ky*ky + kz*kz;
    float coef = 0.0f;
    if (idx != 0) {
        float ikk = 1.0f / kk;
        coef = -ikk * __expf(-0.09f * ikk - kk * kk) * (1.0f / 2097152.0f);
    }
    float2 d = A[idx];
    float pr = d.x * coef, pi = d.y * coef;
    Bxy[idx] = make_float2(pr * ky + pi * kx, pi * ky - pr * kx);
    Cz[idx]  = make_float2(pi * kz, -pr * kz);
}

// ---------------------------------------------------------------------------
__global__ void gather_kernel(const float* __restrict__ pos,
                              const float* __restrict__ vel,
                              const float* __restrict__ drift,
                              const float2* __restrict__ Fxy,
                              const float2* __restrict__ Fz,
                              float* __restrict__ out, int N) {
    int n = blockIdx.x * 256 + threadIdx.x;
    if (n >= N) return;
    float px = pos[3*n+0], py = pos[3*n+1], pz = pos[3*n+2];
    float f0x = floorf(px), f0y = floorf(py), f0z = floorf(pz);
    int ix = ((int)f0x) & 127, iy = ((int)f0y) & 127, iz = ((int)f0z) & 127;
    float dx = px - f0x, dy = py - f0y, dz = pz - f0z;
    float wx[2] = {1.0f - dx, dx};
    float wy[2] = {1.0f - dy, dy};
    float wz[2] = {1.0f - dz, dz};
    int xi[2] = {ix, (ix + 1) & 127};
    int yi[2] = {iy, (iy + 1) & 127};
    int zi[2] = {iz, (iz + 1) & 127};
    float fx = 0.0f, fy = 0.0f, fzv = 0.0f;
#pragma unroll
    for (int a = 0; a < 2; a++)
#pragma unroll
        for (int b = 0; b < 2; b++)
#pragma unroll
            for (int c = 0; c < 2; c++) {
                int   idx = xi[a]*M2 + yi[b]*MESHN + zi[c];
                float w   = wx[a]*wy[b]*wz[c];
                float2 v  = Fxy[idx];
                fx  += w * v.x;
                fy  += w * v.y;
                fzv += w * Fz[idx].x;
            }
    float sc = 0.2f / drift[0];
    out[3*n+0] = px;
    out[3*n+1] = py;
    out[3*n+2] = pz;
    float* ov = out + (size_t)3 * N;
    ov[3*n+0] = vel[3*n+0] + fx  * sc;
    ov[3*n+1] = vel[3*n+1] + fy  * sc;
    ov[3*n+2] = vel[3*n+2] + fzv * sc;
}

// ---------------------------------------------------------------------------
extern "C" void kernel_launch(void* const* d_in, const int* in_sizes, int n_in,
                              void* d_out, int out_size) {
    const float* pos   = (const float*)d_in[0];
    const float* vel   = (const float*)d_in[1];
    const float* drift = (const float*)d_in[2];
    float* out = (float*)d_out;
    int N = in_sizes[0] / 3;

    void *pR, *pA, *pB, *pC;
    cudaGetSymbolAddress(&pR, g_real);
    cudaGetSymbolAddress(&pA, g_A);
    cudaGetSymbolAddress(&pB, g_B);
    cudaGetSymbolAddress(&pC, g_C);
    float*  R = (float*)pR;
    float2* A = (float2*)pA;
    float2* B = (float2*)pB;
    float2* C = (float2*)pC;

    // 1. zero + CIC paint
    zero_kernel<<<M3 / 256, 256>>>(R);
    paint_kernel<<<(N + 255) / 256, 256>>>(pos, R, N);

    // 2. forward 3D FFT: real -> A (z), A -> B (y), B -> A (x)
    fft_pass<1,     128, 2048, false, true ><<<1024,          256>>>(nullptr, R, A);
    fft_pass<128,   1,   16,   false, false><<<dim3(8, 128),  256>>>(A, nullptr, B);
    fft_pass<16384, 1,   16,   false, false><<<1024,          256>>>(B, nullptr, A);

    // 3. spectral filter: A(delta_k) -> B (Fx+iFy spectrum), C (Fz spectrum)
    filter_kernel<<<M3 / 256, 256>>>(A, B, C);

    // 4. inverse 3D FFT for packed (Fx, Fy): B -> A -> B -> A
    fft_pass<1,     128, 2048, true, false><<<1024,         256>>>(B, nullptr, A);
    fft_pass<128,   1,   16,   true, false><<<dim3(8, 128), 256>>>(A, nullptr, B);
    fft_pass<16384, 1,   16,   true, false><<<1024,         256>>>(B, nullptr, A);

    // 5. inverse 3D FFT for Fz: C -> B -> C -> B
    fft_pass<1,     128, 2048, true, false><<<1024,         256>>>(C, nullptr, B);
    fft_pass<128,   1,   16,   true, false><<<dim3(8, 128), 256>>>(B, nullptr, C);
    fft_pass<16384, 1,   16,   true, false><<<1024,         256>>>(C, nullptr, B);

    // 6. CIC gather + velocity boost + pos passthrough
    gather_kernel<<<(N + 255) / 256, 256>>>(pos, vel, drift, A, B, out, N);
}

// round 2
// speedup vs baseline: 1.5500x; 1.5500x over previous
#include <cuda_runtime.h>
#include <math.h>

#define MESHN 128
#define M2    16384
#define M3    2097152
#define SW    145   // smem line stride in float2 (odd -> de-conflicts cross-line access)

// Scratch (static device globals — no runtime allocation)
__device__ float  g_real[M3];
__device__ float2 g_A[M3];
__device__ float2 g_B[M3];
__device__ float2 g_C[M3];

// ---------------------------------------------------------------------------
__device__ __forceinline__ float2 cadd(float2 a, float2 b){ return make_float2(a.x+b.x, a.y+b.y); }
__device__ __forceinline__ float2 csub(float2 a, float2 b){ return make_float2(a.x-b.x, a.y-b.y); }
__device__ __forceinline__ float2 cmul(float2 a, float2 b){ return make_float2(a.x*b.x-a.y*b.y, a.x*b.y+a.y*b.x); }
template<int SGN>
__device__ __forceinline__ float2 cmulJ(float2 a){   // multiply by (0, SGN)
    return make_float2((float)(-SGN)*a.y, (float)SGN*a.x);
}

// natural-layout smem index with pad: +8 float2 after the first 64 (separates t1 halves)
__device__ __forceinline__ int nidx(int i){ return i + ((i>>6)<<3); }

// 8-point DFT in registers, DIF, natural-order outputs. SGN=-1 fwd, +1 inv.
template<int SGN>
__device__ __forceinline__ void dft8(float2* a){
    const float R2 = 0.70710678118654752f;
    const float2 W1 = make_float2( R2, (float)SGN*R2);
    const float2 W3 = make_float2(-R2, (float)SGN*R2);
    float2 t0=cadd(a[0],a[4]), t4=csub(a[0],a[4]);
    float2 t1=cadd(a[1],a[5]), t5=cmul(csub(a[1],a[5]),W1);
    float2 t2=cadd(a[2],a[6]), t6=cmulJ<SGN>(csub(a[2],a[6]));
    float2 t3=cadd(a[3],a[7]), t7=cmul(csub(a[3],a[7]),W3);
    float2 u0=cadd(t0,t2), u2=csub(t0,t2);
    float2 u1=cadd(t1,t3), u3=cmulJ<SGN>(csub(t1,t3));
    a[0]=cadd(u0,u1); a[4]=csub(u0,u1);
    a[2]=cadd(u2,u3); a[6]=csub(u2,u3);
    float2 v0=cadd(t4,t6), v2=csub(t4,t6);
    float2 v1=cadd(t5,t7), v3=cmulJ<SGN>(csub(t5,t7));
    a[1]=cadd(v0,v1); a[5]=csub(v0,v1);
    a[3]=cadd(v2,v3); a[7]=csub(v2,v3);
}

// 128-pt FFT: 16 threads per line (v = thread-in-line), 8 regs per thread.
// Input:  r[n2] = x[v + 16*n2] (natural order).
// Output: r[j]  = X[k2 + 8*j + 64*t1],  k2 = v>>1, t1 = v&1.
// Uses smem line L for one transpose; 3 internal __syncthreads().
template<int SGN>
__device__ __forceinline__ void fft128(float2* r, float2* s, int L, int v){
    __syncthreads();                       // all callers' smem reads complete
    dft8<SGN>(r);                          // A[k2] over n2
    float sa, ca;                          // twiddle W128^{v*k2}
    __sincosf((float)SGN * 0.049087385212340526f * (float)v, &sa, &ca);
    float2 w = make_float2(ca, sa);
    float2 t = w;
    #pragma unroll
    for(int k2=1;k2<8;k2++){ r[k2]=cmul(r[k2],t); t=cmul(t,w); }
    float2* sl = s + L*SW;
    #pragma unroll
    for(int k2=0;k2<8;k2++) sl[k2*18 + v] = r[k2];   // transpose (18-stride: conflict-free)
    __syncthreads();
    int k2 = v>>1, t1 = v&1;
    #pragma unroll
    for(int q=0;q<8;q++) r[q] = sl[k2*18 + t1 + 2*q];
    __syncthreads();                       // smem free for caller after this
    dft8<SGN>(r);                          // C[j] over q
    if (t1){                               // odd: pre-multiply by W16^j
        const float2 w16 = make_float2(0.92387953251128674f, (float)SGN*0.38268343236508977f);
        float2 tt = w16;
        #pragma unroll
        for(int j=1;j<8;j++){ r[j]=cmul(r[j],tt); tt=cmul(tt,w16); }
    }
    #pragma unroll
    for(int j=0;j<8;j++){                  // pair combine: Y[j] = E + W*O ; Y[j+8] = E - W*O
        float px = __shfl_xor_sync(0xFFFFFFFFu, r[j].x, 1);
        float py = __shfl_xor_sync(0xFFFFFFFFu, r[j].y, 1);
        if (t1==0) r[j] = make_float2(r[j].x+px, r[j].y+py);
        else       r[j] = make_float2(px-r[j].x, py-r[j].y);
    }
}

// ---------------------------------------------------------------------------
// Generic 1-axis FFT pass. 16 lines x 128 pts per block, 256 threads.
// element = base + l*LSTRIDE + i*ISTRIDE, base = blockIdx.y*M2 + blockIdx.x*XBS
template<int ISTRIDE,int LSTRIDE,int XBS,int SGN,bool REAL_IN>
__global__ void __launch_bounds__(256)
fft_pass(const float2* __restrict__ in, const float* __restrict__ rin,
         float2* __restrict__ out){
    __shared__ float2 s[16*SW];
    int tid=threadIdx.x, L=tid>>4, v=tid&15;
    int base = blockIdx.y*M2 + blockIdx.x*XBS;
    float2 r[8];
    if (ISTRIDE==1){
        // contiguous lines: direct coalesced register load
        #pragma unroll
        for(int n2=0;n2<8;n2++){
            int g = base + L*LSTRIDE + (v + 16*n2);
            r[n2] = REAL_IN ? make_float2(rin[g], 0.f) : in[g];
        }
    } else {
        // strided lines: stage coalesced through smem
        #pragma unroll
        for(int k=0;k<8;k++){
            int e=tid+k*256; int i=e>>4, l=e&15;
            s[l*SW + nidx(i)] = in[base + l*LSTRIDE + i*ISTRIDE];
        }
        __syncthreads();
        #pragma unroll
        for(int n2=0;n2<8;n2++) r[n2] = s[L*SW + nidx(v + 16*n2)];
    }
    fft128<SGN>(r, s, L, v);
    int k2=v>>1, t1=v&1;
    #pragma unroll
    for(int j=0;j<8;j++){ int i=k2+8*j+64*t1; s[L*SW+nidx(i)] = r[j]; }
    __syncthreads();
    #pragma unroll
    for(int k=0;k<8;k++){
        int e=tid+k*256; int l,i;
        if (ISTRIDE==1){ l=e>>7; i=e&127; } else { i=e>>4; l=e&15; }
        out[base + l*LSTRIDE + i*ISTRIDE] = s[l*SW+nidx(i)];
    }
}

// ---------------------------------------------------------------------------
// Fused x-axis: fwd FFT -> spectral filter -> inverse FFT (Fxy) -> inverse FFT (Fz)
// x-lines: element = base + l + i*M2, base = blockIdx.x*16; (y,z) from base+l.
__global__ void __launch_bounds__(256)
fft_x_fused(const float2* __restrict__ in, float2* __restrict__ outXY,
            float2* __restrict__ outZ){
    __shared__ float2 s[16*SW];
    int tid=threadIdx.x, L=tid>>4, v=tid&15;
    int base = blockIdx.x*16;
    float2 r[8];
    #pragma unroll
    for(int k=0;k<8;k++){ int e=tid+k*256; int i=e>>4, l=e&15;
        s[l*SW+nidx(i)] = in[base + l + i*M2]; }
    __syncthreads();
    #pragma unroll
    for(int n2=0;n2<8;n2++) r[n2] = s[L*SW + nidx(v + 16*n2)];
    fft128<-1>(r, s, L, v);

    // ---- spectral filter (thread holds delta_k at kx index i = k2+8j+64t1)
    int k2=v>>1, t1=v&1;
    int ylz = base + L;
    int y = ylz>>7, z = ylz&127;
    const float ku = 0.049087385212340526f;     // 2*pi/128
    float ky = (float)((y<64)?y:y-128)*ku;
    float kz = (float)((z<64)?z:z-128)*ku;
    float kyz2 = ky*ky + kz*kz;
    float2 fz[8];
    #pragma unroll
    for(int j=0;j<8;j++){
        int i = k2+8*j+64*t1;
        float kx = (float)((i<64)?i:i-128)*ku;
        float kk = kx*kx + kyz2;
        float coef = 0.f;
        if (kk > 0.f){
            float ikk = 1.f/kk;
            coef = -ikk * __expf(-0.09f*ikk - kk*kk) * (1.f/2097152.f);
        }
        float pr = r[j].x*coef, pi = r[j].y*coef;
        r[j]  = make_float2(pr*ky + pi*kx, pi*ky - pr*kx);  // Fx_k + i*Fy_k
        fz[j] = make_float2(pi*kz, -pr*kz);                 // Fz_k
    }

    // ---- inverse x on Fxy (Fz spectrum parked in regs)
    #pragma unroll
    for(int j=0;j<8;j++){ int i=k2+8*j+64*t1; s[L*SW+nidx(i)] = r[j]; }
    __syncthreads();
    #pragma unroll
    for(int n2=0;n2<8;n2++) r[n2] = s[L*SW + nidx(v + 16*n2)];
    fft128<1>(r, s, L, v);
    #pragma unroll
    for(int j=0;j<8;j++){ int i=k2+8*j+64*t1; s[L*SW+nidx(i)] = r[j]; }
    __syncthreads();
    #pragma unroll
    for(int k=0;k<8;k++){ int e=tid+k*256; int i=e>>4, l=e&15;
        outXY[base + l + i*M2] = s[l*SW+nidx(i)]; }
    __syncthreads();

    // ---- inverse x on Fz
    #pragma unroll
    for(int j=0;j<8;j++){ int i=k2+8*j+64*t1; s[L*SW+nidx(i)] = fz[j]; }
    __syncthreads();
    #pragma unroll
    for(int n2=0;n2<8;n2++) r[n2] = s[L*SW + nidx(v + 16*n2)];
    fft128<1>(r, s, L, v);
    #pragma unroll
    for(int j=0;j<8;j++){ int i=k2+8*j+64*t1; s[L*SW+nidx(i)] = r[j]; }
    __syncthreads();
    #pragma unroll
    for(int k=0;k<8;k++){ int e=tid+k*256; int i=e>>4, l=e&15;
        outZ[base + l + i*M2] = s[l*SW+nidx(i)]; }
}

// ---------------------------------------------------------------------------
__global__ void zero_kernel(float4* __restrict__ r){
    r[blockIdx.x*256 + threadIdx.x] = make_float4(0.f,0.f,0.f,0.f);
}

__global__ void paint_kernel(const float* __restrict__ pos,
                             float* __restrict__ grid, int N){
    int n = blockIdx.x*256 + threadIdx.x;
    if (n >= N) return;
    float px = pos[3*n+0], py = pos[3*n+1], pz = pos[3*n+2];
    float f0x = floorf(px), f0y = floorf(py), f0z = floorf(pz);
    int ix = ((int)f0x)&127, iy = ((int)f0y)&127, iz = ((int)f0z)&127;
    float dx = px-f0x, dy = py-f0y, dz = pz-f0z;
    float wx[2]={1.f-dx,dx}, wy[2]={1.f-dy,dy}, wz[2]={1.f-dz,dz};
    int xi[2]={ix,(ix+1)&127}, yi[2]={iy,(iy+1)&127}, zi[2]={iz,(iz+1)&127};
#pragma unroll
    for(int a=0;a<2;a++)
#pragma unroll
    for(int b=0;b<2;b++)
#pragma unroll
    for(int c=0;c<2;c++)
        atomicAdd(&grid[xi[a]*M2 + yi[b]*MESHN + zi[c]], wx[a]*wy[b]*wz[c]);
}

__global__ void gather_kernel(const float* __restrict__ pos,
                              const float* __restrict__ vel,
                              const float* __restrict__ drift,
                              const float2* __restrict__ Fxy,
                              const float2* __restrict__ Fz,
                              float* __restrict__ out, int N){
    int n = blockIdx.x*256 + threadIdx.x;
    if (n >= N) return;
    float px = pos[3*n+0], py = pos[3*n+1], pz = pos[3*n+2];
    float f0x = floorf(px), f0y = floorf(py), f0z = floorf(pz);
    int ix = ((int)f0x)&127, iy = ((int)f0y)&127, iz = ((int)f0z)&127;
    float dx = px-f0x, dy = py-f0y, dz = pz-f0z;
    float wx[2]={1.f-dx,dx}, wy[2]={1.f-dy,dy}, wz[2]={1.f-dz,dz};
    int xi[2]={ix,(ix+1)&127}, yi[2]={iy,(iy+1)&127}, zi[2]={iz,(iz+1)&127};
    float fx=0.f, fy=0.f, fzv=0.f;
#pragma unroll
    for(int a=0;a<2;a++)
#pragma unroll
    for(int b=0;b<2;b++)
#pragma unroll
    for(int c=0;c<2;c++){
        int   idx = xi[a]*M2 + yi[b]*MESHN + zi[c];
        float w   = wx[a]*wy[b]*wz[c];
        float2 vv = Fxy[idx];
        fx  += w*vv.x;
        fy  += w*vv.y;
        fzv += w*Fz[idx].x;
    }
    float sc = 0.2f / drift[0];
    out[3*n+0]=px; out[3*n+1]=py; out[3*n+2]=pz;
    float* ov = out + (size_t)3*N;
    ov[3*n+0]=vel[3*n+0]+fx*sc;
    ov[3*n+1]=vel[3*n+1]+fy*sc;
    ov[3*n+2]=vel[3*n+2]+fzv*sc;
}

// ---------------------------------------------------------------------------
extern "C" void kernel_launch(void* const* d_in, const int* in_sizes, int n_in,
                              void* d_out, int out_size){
    const float* pos   = (const float*)d_in[0];
    const float* vel   = (const float*)d_in[1];
    const float* drift = (const float*)d_in[2];
    float* out = (float*)d_out;
    int N = in_sizes[0] / 3;

    void *pR,*pA,*pB,*pC;
    cudaGetSymbolAddress(&pR, g_real);
    cudaGetSymbolAddress(&pA, g_A);
    cudaGetSymbolAddress(&pB, g_B);
    cudaGetSymbolAddress(&pC, g_C);
    float*  R = (float*)pR;
    float2* A = (float2*)pA;
    float2* B = (float2*)pB;
    float2* C = (float2*)pC;

    // 1. zero + CIC paint
    zero_kernel<<<M3/1024, 256>>>((float4*)R);
    paint_kernel<<<(N+255)/256, 256>>>(pos, R, N);

    // 2. forward: z then y
    fft_pass<1,   128, 2048, -1, true ><<<1024,         256>>>(nullptr, R, A);
    fft_pass<128, 1,   16,   -1, false><<<dim3(8,128),  256>>>(A, nullptr, B);

    // 3. fused: x-fwd + filter + x-inv(Fxy)->A + x-inv(Fz)->C
    fft_x_fused<<<1024, 256>>>(B, A, C);

    // 4. inverse y,z for Fxy: A->B->A
    fft_pass<128, 1,   16,   1, false><<<dim3(8,128), 256>>>(A, nullptr, B);
    fft_pass<1,   128, 2048, 1, false><<<1024,        256>>>(B, nullptr, A);

    // 5. inverse y,z for Fz: C->B->C
    fft_pass<128, 1,   16,   1, false><<<dim3(8,128), 256>>>(C, nullptr, B);
    fft_pass<1,   128, 2048, 1, false><<<1024,        256>>>(B, nullptr, C);

    // 6. CIC gather + velocity boost
    gather_kernel<<<(N+255)/256, 256>>>(pos, vel, drift, A, C, out, N);
}

// round 3
// speedup vs baseline: 1.8377x; 1.1856x over previous
#include <cuda_runtime.h>
#include <math.h>

#define MESHN 128
#define M2    16384
#define M3    2097152
#define SW    145    // fft128 transpose scratch line stride (float2)
#define PST   137    // plane row stride (float2)

// Scratch (static device globals — no runtime allocation)
__device__ float  g_real[M3];
__device__ float2 g_A[M3];
__device__ float2 g_B[M3];
__device__ float2 g_C[M3];
__device__ float4 g_G[M3];

// ---------------------------------------------------------------------------
__device__ __forceinline__ float2 cadd(float2 a, float2 b){ return make_float2(a.x+b.x, a.y+b.y); }
__device__ __forceinline__ float2 csub(float2 a, float2 b){ return make_float2(a.x-b.x, a.y-b.y); }
__device__ __forceinline__ float2 cmul(float2 a, float2 b){ return make_float2(a.x*b.x-a.y*b.y, a.x*b.y+a.y*b.x); }
template<int SGN>
__device__ __forceinline__ float2 cmulJ(float2 a){ return make_float2((float)(-SGN)*a.y, (float)SGN*a.x); }

// padded index: +8 after each 64 (bank de-conflict)
__device__ __forceinline__ int nidx(int i){ return i + ((i>>6)<<3); }

template<int SGN>
__device__ __forceinline__ void dft8(float2* a){
    const float R2 = 0.70710678118654752f;
    const float2 W1 = make_float2( R2, (float)SGN*R2);
    const float2 W3 = make_float2(-R2, (float)SGN*R2);
    float2 t0=cadd(a[0],a[4]), t4=csub(a[0],a[4]);
    float2 t1=cadd(a[1],a[5]), t5=cmul(csub(a[1],a[5]),W1);
    float2 t2=cadd(a[2],a[6]), t6=cmulJ<SGN>(csub(a[2],a[6]));
    float2 t3=cadd(a[3],a[7]), t7=cmul(csub(a[3],a[7]),W3);
    float2 u0=cadd(t0,t2), u2=csub(t0,t2);
    float2 u1=cadd(t1,t3), u3=cmulJ<SGN>(csub(t1,t3));
    a[0]=cadd(u0,u1); a[4]=csub(u0,u1);
    a[2]=cadd(u2,u3); a[6]=csub(u2,u3);
    float2 v0=cadd(t4,t6), v2=csub(t4,t6);
    float2 v1=cadd(t5,t7), v3=cmulJ<SGN>(csub(t5,t7));
    a[1]=cadd(v0,v1); a[5]=csub(v0,v1);
    a[3]=cadd(v2,v3); a[7]=csub(v2,v3);
}

// 128-pt FFT: 16 threads/line, 8 regs/thread. In: r[n2]=x[v+16n2].
// Out: r[j]=X[k2+8j+64t1], k2=v>>1, t1=v&1. Uses scratch line L, 3 syncthreads.
template<int SGN>
__device__ __forceinline__ void fft128(float2* r, float2* s, int L, int v){
    __syncthreads();
    dft8<SGN>(r);
    float sa, ca;
    __sincosf((float)SGN * 0.049087385212340526f * (float)v, &sa, &ca);
    float2 w = make_float2(ca, sa);
    float2 t = w;
    #pragma unroll
    for(int k2=1;k2<8;k2++){ r[k2]=cmul(r[k2],t); t=cmul(t,w); }
    float2* sl = s + L*SW;
    #pragma unroll
    for(int k2=0;k2<8;k2++) sl[k2*18 + v] = r[k2];
    __syncthreads();
    int k2 = v>>1, t1 = v&1;
    #pragma unroll
    for(int q=0;q<8;q++) r[q] = sl[k2*18 + t1 + 2*q];
    __syncthreads();
    dft8<SGN>(r);
    if (t1){
        const float2 w16 = make_float2(0.92387953251128674f, (float)SGN*0.38268343236508977f);
        float2 tt = w16;
        #pragma unroll
        for(int j=1;j<8;j++){ r[j]=cmul(r[j],tt); tt=cmul(tt,w16); }
    }
    #pragma unroll
    for(int j=0;j<8;j++){
        float px = __shfl_xor_sync(0xFFFFFFFFu, r[j].x, 1);
        float py = __shfl_xor_sync(0xFFFFFFFFu, r[j].y, 1);
        if (t1==0) r[j] = make_float2(r[j].x+px, r[j].y+py);
        else       r[j] = make_float2(px-r[j].x, py-r[j].y);
    }
}

// ---------------------------------------------------------------------------
// In-smem 2D FFT of a 128x128 plane: z-axis (stride 1) then y-axis (stride PST).
// 512 threads = 32 concurrent lines, 4 iterations per axis.
template<int SGN>
__device__ __forceinline__ void plane_fft2d(float2* plane, float2* scratch){
    int tid=threadIdx.x, L=tid>>4, v=tid&15, k2=v>>1, t1=v&1;
    float2 r[8];
    #pragma unroll
    for(int it=0; it<4; it++){
        float2* row = plane + nidx(it*32+L)*PST;
        #pragma unroll
        for(int n2=0;n2<8;n2++) r[n2]=row[nidx(v+16*n2)];
        fft128<SGN>(r, scratch, L, v);
        #pragma unroll
        for(int j=0;j<8;j++) row[nidx(k2+8*j+64*t1)]=r[j];
    }
    __syncthreads();
    #pragma unroll
    for(int it=0; it<4; it++){
        int zc = nidx(it*32+L);
        #pragma unroll
        for(int n2=0;n2<8;n2++) r[n2]=plane[nidx(v+16*n2)*PST + zc];
        fft128<SGN>(r, scratch, L, v);
        #pragma unroll
        for(int j=0;j<8;j++) plane[nidx(k2+8*j+64*t1)*PST + zc]=r[j];
    }
    __syncthreads();
}

#define PLANE_F2   (136*PST)                 // 18,632 float2
#define SMEM_PLANE ((PLANE_F2 + 32*SW)*8)    // bytes

// Forward: real grid plane -> 2D FFT (z,y) -> complex out. grid.x = 128 (x).
__global__ void __launch_bounds__(512)
fft_plane_fwd(const float* __restrict__ rin, float2* __restrict__ out){
    extern __shared__ float2 sm[];
    float2* plane = sm; float2* scratch = sm + PLANE_F2;
    int tid = threadIdx.x;
    size_t base = (size_t)blockIdx.x * M2;
    #pragma unroll
    for(int k=0;k<32;k++){
        int e = tid + k*512;
        plane[nidx(e>>7)*PST + nidx(e&127)] = make_float2(rin[base+e], 0.f);
    }
    __syncthreads();
    plane_fft2d<-1>(plane, scratch);
    #pragma unroll
    for(int k=0;k<32;k++){
        int e = tid + k*512;
        out[base+e] = plane[nidx(e>>7)*PST + nidx(e&127)];
    }
}

// Inverse planes. Flat grid of 192 blocks:
//  b in [0,128): Fxy plane x=b -> write G.xy
//  b in [128,192): pack Fz planes x0=2q, x1=2q+1 (q=b-128) as Ca + i*Cb -> G.z
__global__ void __launch_bounds__(512)
fft_plane_inv(const float2* __restrict__ inXY, const float2* __restrict__ inZ,
              float4* __restrict__ G){
    extern __shared__ float2 sm[];
    float2* plane = sm; float2* scratch = sm + PLANE_F2;
    int b = blockIdx.x, tid = threadIdx.x;
    if (b < 128){
        size_t base = (size_t)b * M2;
        #pragma unroll
        for(int k=0;k<32;k++){
            int e = tid + k*512;
            plane[nidx(e>>7)*PST + nidx(e&127)] = inXY[base+e];
        }
        __syncthreads();
        plane_fft2d<1>(plane, scratch);
        float2* g2 = (float2*)G;
        #pragma unroll
        for(int k=0;k<32;k++){
            int e = tid + k*512;
            g2[2*(base+e)] = plane[nidx(e>>7)*PST + nidx(e&127)];
        }
    } else {
        int q = b - 128;
        size_t b0 = (size_t)(2*q) * M2, b1 = b0 + M2;
        #pragma unroll
        for(int k=0;k<32;k++){
            int e = tid + k*512;
            float2 a = inZ[b0+e], c = inZ[b1+e];
            plane[nidx(e>>7)*PST + nidx(e&127)] = make_float2(a.x - c.y, a.y + c.x);
        }
        __syncthreads();
        plane_fft2d<1>(plane, scratch);
        float* gf = (float*)G;
        #pragma unroll
        for(int k=0;k<32;k++){
            int e = tid + k*512;
            float2 vv = plane[nidx(e>>7)*PST + nidx(e&127)];
            gf[4*(b0+e)+2] = vv.x;
            gf[4*(b1+e)+2] = vv.y;
        }
    }
}

// ---------------------------------------------------------------------------
// Fused x-axis: fwd FFT -> spectral filter -> inverse FFT (Fxy) -> inverse (Fz)
__global__ void __launch_bounds__(256)
fft_x_fused(const float2* __restrict__ in, float2* __restrict__ outXY,
            float2* __restrict__ outZ){
    __shared__ float2 s[16*SW];
    int tid=threadIdx.x, L=tid>>4, v=tid&15;
    int base = blockIdx.x*16;
    float2 r[8];
    #pragma unroll
    for(int k=0;k<8;k++){ int e=tid+k*256; int i=e>>4, l=e&15;
        s[l*SW+nidx(i)] = in[base + l + i*M2]; }
    __syncthreads();
    #pragma unroll
    for(int n2=0;n2<8;n2++) r[n2] = s[L*SW + nidx(v + 16*n2)];
    fft128<-1>(r, s, L, v);

    int k2=v>>1, t1=v&1;
    int ylz = base + L;
    int y = ylz>>7, z = ylz&127;
    const float ku = 0.049087385212340526f;
    float ky = (float)((y<64)?y:y-128)*ku;
    float kz = (float)((z<64)?z:z-128)*ku;
    float kyz2 = ky*ky + kz*kz;
    float2 fz[8];
    #pragma unroll
    for(int j=0;j<8;j++){
        int i = k2+8*j+64*t1;
        float kx = (float)((i<64)?i:i-128)*ku;
        float kk = kx*kx + kyz2;
        float coef = 0.f;
        if (kk > 0.f){
            float ikk = 1.f/kk;
            coef = -ikk * __expf(-0.09f*ikk - kk*kk) * (1.f/2097152.f);
        }
        float pr = r[j].x*coef, pi = r[j].y*coef;
        r[j]  = make_float2(pr*ky + pi*kx, pi*ky - pr*kx);
        fz[j] = make_float2(pi*kz, -pr*kz);
    }

    #pragma unroll
    for(int j=0;j<8;j++){ int i=k2+8*j+64*t1; s[L*SW+nidx(i)] = r[j]; }
    __syncthreads();
    #pragma unroll
    for(int n2=0;n2<8;n2++) r[n2] = s[L*SW + nidx(v + 16*n2)];
    fft128<1>(r, s, L, v);
    #pragma unroll
    for(int j=0;j<8;j++){ int i=k2+8*j+64*t1; s[L*SW+nidx(i)] = r[j]; }
    __syncthreads();
    #pragma unroll
    for(int k=0;k<8;k++){ int e=tid+k*256; int i=e>>4, l=e&15;
        outXY[base + l + i*M2] = s[l*SW+nidx(i)]; }
    __syncthreads();

    #pragma unroll
    for(int j=0;j<8;j++){ int i=k2+8*j+64*t1; s[L*SW+nidx(i)] = fz[j]; }
    __syncthreads();
    #pragma unroll
    for(int n2=0;n2<8;n2++) r[n2] = s[L*SW + nidx(v + 16*n2)];
    fft128<1>(r, s, L, v);
    #pragma unroll
    for(int j=0;j<8;j++){ int i=k2+8*j+64*t1; s[L*SW+nidx(i)] = r[j]; }
    __syncthreads();
    #pragma unroll
    for(int k=0;k<8;k++){ int e=tid+k*256; int i=e>>4, l=e&15;
        outZ[base + l + i*M2] = s[l*SW+nidx(i)]; }
}

// ---------------------------------------------------------------------------
__global__ void zero_kernel(float4* __restrict__ r){
    r[blockIdx.x*256 + threadIdx.x] = make_float4(0.f,0.f,0.f,0.f);
}

__global__ void paint_kernel(const float* __restrict__ pos,
                             float* __restrict__ grid, int N){
    int n = blockIdx.x*256 + threadIdx.x;
    if (n >= N) return;
    float px = pos[3*n+0], py = pos[3*n+1], pz = pos[3*n+2];
    float f0x = floorf(px), f0y = floorf(py), f0z = floorf(pz);
    int ix = ((int)f0x)&127, iy = ((int)f0y)&127, iz = ((int)f0z)&127;
    float dx = px-f0x, dy = py-f0y, dz = pz-f0z;
    float wx[2]={1.f-dx,dx}, wy[2]={1.f-dy,dy}, wz[2]={1.f-dz,dz};
    int xi[2]={ix,(ix+1)&127}, yi[2]={iy,(iy+1)&127}, zi[2]={iz,(iz+1)&127};
#pragma unroll
    for(int a=0;a<2;a++)
#pragma unroll
    for(int b=0;b<2;b++)
#pragma unroll
    for(int c=0;c<2;c++)
        atomicAdd(&grid[xi[a]*M2 + yi[b]*MESHN + zi[c]], wx[a]*wy[b]*wz[c]);
}

__global__ void gather_kernel(const float* __restrict__ pos,
                              const float* __restrict__ vel,
                              const float* __restrict__ drift,
                              const float4* __restrict__ G,
                              float* __restrict__ out, int N){
    int n = blockIdx.x*256 + threadIdx.x;
    if (n >= N) return;
    float px = pos[3*n+0], py = pos[3*n+1], pz = pos[3*n+2];
    float f0x = floorf(px), f0y = floorf(py), f0z = floorf(pz);
    int ix = ((int)f0x)&127, iy = ((int)f0y)&127, iz = ((int)f0z)&127;
    float dx = px-f0x, dy = py-f0y, dz = pz-f0z;
    float wx[2]={1.f-dx,dx}, wy[2]={1.f-dy,dy}, wz[2]={1.f-dz,dz};
    int xi[2]={ix,(ix+1)&127}, yi[2]={iy,(iy+1)&127}, zi[2]={iz,(iz+1)&127};
    float fx=0.f, fy=0.f, fzv=0.f;
#pragma unroll
    for(int a=0;a<2;a++)
#pragma unroll
    for(int b=0;b<2;b++)
#pragma unroll
    for(int c=0;c<2;c++){
        float4 v4 = G[xi[a]*M2 + yi[b]*MESHN + zi[c]];
        float w = wx[a]*wy[b]*wz[c];
        fx += w*v4.x; fy += w*v4.y; fzv += w*v4.z;
    }
    float sc = 0.2f / drift[0];
    out[3*n+0]=px; out[3*n+1]=py; out[3*n+2]=pz;
    float* ov = out + (size_t)3*N;
    ov[3*n+0]=vel[3*n+0]+fx*sc;
    ov[3*n+1]=vel[3*n+1]+fy*sc;
    ov[3*n+2]=vel[3*n+2]+fzv*sc;
}

// ---------------------------------------------------------------------------
extern "C" void kernel_launch(void* const* d_in, const int* in_sizes, int n_in,
                              void* d_out, int out_size){
    const float* pos   = (const float*)d_in[0];
    const float* vel   = (const float*)d_in[1];
    const float* drift = (const float*)d_in[2];
    float* out = (float*)d_out;
    int N = in_sizes[0] / 3;

    void *pR,*pA,*pB,*pC,*pG;
    cudaGetSymbolAddress(&pR, g_real);
    cudaGetSymbolAddress(&pA, g_A);
    cudaGetSymbolAddress(&pB, g_B);
    cudaGetSymbolAddress(&pC, g_C);
    cudaGetSymbolAddress(&pG, g_G);
    float*  R = (float*)pR;
    float2* A = (float2*)pA;
    float2* B = (float2*)pB;
    float2* C = (float2*)pC;
    float4* G = (float4*)pG;

    cudaFuncSetAttribute(fft_plane_fwd, cudaFuncAttributeMaxDynamicSharedMemorySize, SMEM_PLANE);
    cudaFuncSetAttribute(fft_plane_inv, cudaFuncAttributeMaxDynamicSharedMemorySize, SMEM_PLANE);

    // 1. zero + CIC paint
    zero_kernel<<<M3/1024, 256>>>((float4*)R);
    paint_kernel<<<(N+255)/256, 256>>>(pos, R, N);

    // 2. forward z+y (per-x plane): R -> B
    fft_plane_fwd<<<128, 512, SMEM_PLANE>>>(R, B);

    // 3. fused x: fwd + filter + x-inv(Fxy)->A, x-inv(Fz)->C
    fft_x_fused<<<1024, 256>>>(B, A, C);

    // 4. inverse y+z planes: A -> G.xy ; C (packed pairs) -> G.z
    fft_plane_inv<<<192, 512, SMEM_PLANE>>>(A, C, G);

    // 5. CIC gather + velocity boost
    gather_kernel<<<(N+255)/256, 256>>>(pos, vel, drift, G, out, N);
}

// round 4
// speedup vs baseline: 2.1364x; 1.1625x over previous
#include <cuda_runtime.h>
#include <math.h>

#define MESHN 128
#define M2    16384
#define M3    2097152
#define SW    145    // fft128 transpose scratch line stride (float2)
#define PST   137    // plane row stride (float2)

// Scratch (static device globals — no runtime allocation)
__device__ float  g_real[M3];
__device__ float2 g_A[M3];
__device__ float2 g_B[M3];
__device__ float2 g_C[M3];
__device__ float4 g_G[M3];

// ---------------------------------------------------------------------------
__device__ __forceinline__ float2 cadd(float2 a, float2 b){ return make_float2(a.x+b.x, a.y+b.y); }
__device__ __forceinline__ float2 csub(float2 a, float2 b){ return make_float2(a.x-b.x, a.y-b.y); }
__device__ __forceinline__ float2 cmul(float2 a, float2 b){ return make_float2(a.x*b.x-a.y*b.y, a.x*b.y+a.y*b.x); }
template<int SGN>
__device__ __forceinline__ float2 cmulJ(float2 a){ return make_float2((float)(-SGN)*a.y, (float)SGN*a.x); }

// padded index: +8 after each 64 (bank de-conflict)
__device__ __forceinline__ int nidx(int i){ return i + ((i>>6)<<3); }
__device__ __forceinline__ int pidx(int e){ return nidx(e>>7)*PST + nidx(e&127); }

template<int SGN>
__device__ __forceinline__ void dft8(float2* a){
    const float R2 = 0.70710678118654752f;
    const float2 W1 = make_float2( R2, (float)SGN*R2);
    const float2 W3 = make_float2(-R2, (float)SGN*R2);
    float2 t0=cadd(a[0],a[4]), t4=csub(a[0],a[4]);
    float2 t1=cadd(a[1],a[5]), t5=cmul(csub(a[1],a[5]),W1);
    float2 t2=cadd(a[2],a[6]), t6=cmulJ<SGN>(csub(a[2],a[6]));
    float2 t3=cadd(a[3],a[7]), t7=cmul(csub(a[3],a[7]),W3);
    float2 u0=cadd(t0,t2), u2=csub(t0,t2);
    float2 u1=cadd(t1,t3), u3=cmulJ<SGN>(csub(t1,t3));
    a[0]=cadd(u0,u1); a[4]=csub(u0,u1);
    a[2]=cadd(u2,u3); a[6]=csub(u2,u3);
    float2 v0=cadd(t4,t6), v2=csub(t4,t6);
    float2 v1=cadd(t5,t7), v3=cmulJ<SGN>(csub(t5,t7));
    a[1]=cadd(v0,v1); a[5]=csub(v0,v1);
    a[3]=cadd(v2,v3); a[7]=csub(v2,v3);
}

// 128-pt FFT: 16 threads/line, 8 regs/thread. In: r[n2]=x[v+16n2].
// Out: r[j]=X[k2+8j+64t1], k2=v>>1, t1=v&1. Uses scratch line L, 3 syncthreads.
template<int SGN>
__device__ __forceinline__ void fft128(float2* r, float2* s, int L, int v){
    __syncthreads();
    dft8<SGN>(r);
    float sa, ca;
    __sincosf((float)SGN * 0.049087385212340526f * (float)v, &sa, &ca);
    float2 w = make_float2(ca, sa);
    float2 t = w;
    #pragma unroll
    for(int k2=1;k2<8;k2++){ r[k2]=cmul(r[k2],t); t=cmul(t,w); }
    float2* sl = s + L*SW;
    #pragma unroll
    for(int k2=0;k2<8;k2++) sl[k2*18 + v] = r[k2];
    __syncthreads();
    int k2 = v>>1, t1 = v&1;
    #pragma unroll
    for(int q=0;q<8;q++) r[q] = sl[k2*18 + t1 + 2*q];
    __syncthreads();
    dft8<SGN>(r);
    if (t1){
        const float2 w16 = make_float2(0.92387953251128674f, (float)SGN*0.38268343236508977f);
        float2 tt = w16;
        #pragma unroll
        for(int j=1;j<8;j++){ r[j]=cmul(r[j],tt); tt=cmul(tt,w16); }
    }
    #pragma unroll
    for(int j=0;j<8;j++){
        float px = __shfl_xor_sync(0xFFFFFFFFu, r[j].x, 1);
        float py = __shfl_xor_sync(0xFFFFFFFFu, r[j].y, 1);
        if (t1==0) r[j] = make_float2(r[j].x+px, r[j].y+py);
        else       r[j] = make_float2(px-r[j].x, py-r[j].y);
    }
}

// ---------------------------------------------------------------------------
// In-smem 2D FFT of a 128x128 plane. 1024 threads = 64 concurrent lines,
// 2 iterations per axis. z-axis (stride 1) then y-axis (stride PST).
template<int SGN>
__device__ __forceinline__ void plane_fft2d(float2* plane, float2* scratch){
    int tid=threadIdx.x, L=tid>>4, v=tid&15, k2=v>>1, t1=v&1;
    float2 r[8];
    #pragma unroll
    for(int it=0; it<2; it++){
        float2* row = plane + nidx(it*64+L)*PST;
        #pragma unroll
        for(int n2=0;n2<8;n2++) r[n2]=row[nidx(v+16*n2)];
        fft128<SGN>(r, scratch, L, v);
        #pragma unroll
        for(int j=0;j<8;j++) row[nidx(k2+8*j+64*t1)]=r[j];
    }
    __syncthreads();
    #pragma unroll
    for(int it=0; it<2; it++){
        int zc = nidx(it*64+L);
        #pragma unroll
        for(int n2=0;n2<8;n2++) r[n2]=plane[nidx(v+16*n2)*PST + zc];
        fft128<SGN>(r, scratch, L, v);
        #pragma unroll
        for(int j=0;j<8;j++) plane[nidx(k2+8*j+64*t1)*PST + zc]=r[j];
    }
    __syncthreads();
}

#define PLANE_F2   (136*PST)                 // 18,632 float2
#define SMEM_PLANE ((PLANE_F2 + 64*SW)*8)    // 223,296 bytes

// Forward: real grid plane -> 2D FFT (z,y) -> complex out. grid.x = 128 (x).
__global__ void __launch_bounds__(1024, 1)
fft_plane_fwd(const float* __restrict__ rin, float2* __restrict__ out){
    extern __shared__ float2 sm[];
    float2* plane = sm; float2* scratch = sm + PLANE_F2;
    int tid = threadIdx.x;
    size_t base = (size_t)blockIdx.x * M2;
    #pragma unroll
    for(int k=0;k<16;k++){
        int e = tid + k*1024;
        plane[pidx(e)] = make_float2(rin[base+e], 0.f);
    }
    __syncthreads();
    plane_fft2d<-1>(plane, scratch);
    #pragma unroll
    for(int k=0;k<16;k++){
        int e = tid + k*1024;
        out[base+e] = plane[pidx(e)];
    }
}

// Combined inverse: per x-plane, Fz plane FFT (real parts -> regs), then Fxy
// plane FFT, then one coalesced float4 store. 128 blocks = exactly one wave.
__global__ void __launch_bounds__(1024, 1)
fft_plane_inv(const float2* __restrict__ inXY, const float2* __restrict__ inZ,
              float4* __restrict__ G){
    extern __shared__ float2 sm[];
    float2* plane = sm; float2* scratch = sm + PLANE_F2;
    int tid = threadIdx.x;
    size_t base = (size_t)blockIdx.x * M2;

    // --- Fz plane ---
    #pragma unroll
    for(int k=0;k<16;k++){
        int e = tid + k*1024;
        plane[pidx(e)] = inZ[base+e];
    }
    __syncthreads();
    plane_fft2d<1>(plane, scratch);
    float zreg[16];
    #pragma unroll
    for(int k=0;k<16;k++){
        int e = tid + k*1024;
        zreg[k] = plane[pidx(e)].x;       // same-thread read...
        plane[pidx(e)] = inXY[base+e];    // ...then same-thread overwrite: no race
    }
    __syncthreads();

    // --- Fxy plane ---
    plane_fft2d<1>(plane, scratch);
    #pragma unroll
    for(int k=0;k<16;k++){
        int e = tid + k*1024;
        float2 xy = plane[pidx(e)];
        G[base+e] = make_float4(xy.x, xy.y, zreg[k], 0.f);
    }
}

// ---------------------------------------------------------------------------
// Fused x-axis: fwd FFT -> spectral filter -> inverse FFT (Fxy) -> inverse (Fz)
__global__ void __launch_bounds__(256)
fft_x_fused(const float2* __restrict__ in, float2* __restrict__ outXY,
            float2* __restrict__ outZ){
    __shared__ float2 s[16*SW];
    int tid=threadIdx.x, L=tid>>4, v=tid&15;
    int base = blockIdx.x*16;
    float2 r[8];
    #pragma unroll
    for(int k=0;k<8;k++){ int e=tid+k*256; int i=e>>4, l=e&15;
        s[l*SW+nidx(i)] = in[base + l + i*M2]; }
    __syncthreads();
    #pragma unroll
    for(int n2=0;n2<8;n2++) r[n2] = s[L*SW + nidx(v + 16*n2)];
    fft128<-1>(r, s, L, v);

    int k2=v>>1, t1=v&1;
    int ylz = base + L;
    int y = ylz>>7, z = ylz&127;
    const float ku = 0.049087385212340526f;
    float ky = (float)((y<64)?y:y-128)*ku;
    float kz = (float)((z<64)?z:z-128)*ku;
    float kyz2 = ky*ky + kz*kz;
    float2 fz[8];
    #pragma unroll
    for(int j=0;j<8;j++){
        int i = k2+8*j+64*t1;
        float kx = (float)((i<64)?i:i-128)*ku;
        float kk = kx*kx + kyz2;
        float coef = 0.f;
        if (kk > 0.f){
            float ikk = 1.f/kk;
            coef = -ikk * __expf(-0.09f*ikk - kk*kk) * (1.f/2097152.f);
        }
        float pr = r[j].x*coef, pi = r[j].y*coef;
        r[j]  = make_float2(pr*ky + pi*kx, pi*ky - pr*kx);
        fz[j] = make_float2(pi*kz, -pr*kz);
    }

    #pragma unroll
    for(int j=0;j<8;j++){ int i=k2+8*j+64*t1; s[L*SW+nidx(i)] = r[j]; }
    __syncthreads();
    #pragma unroll
    for(int n2=0;n2<8;n2++) r[n2] = s[L*SW + nidx(v + 16*n2)];
    fft128<1>(r, s, L, v);
    #pragma unroll
    for(int j=0;j<8;j++){ int i=k2+8*j+64*t1; s[L*SW+nidx(i)] = r[j]; }
    __syncthreads();
    #pragma unroll
    for(int k=0;k<8;k++){ int e=tid+k*256; int i=e>>4, l=e&15;
        outXY[base + l + i*M2] = s[l*SW+nidx(i)]; }
    __syncthreads();

    #pragma unroll
    for(int j=0;j<8;j++){ int i=k2+8*j+64*t1; s[L*SW+nidx(i)] = fz[j]; }
    __syncthreads();
    #pragma unroll
    for(int n2=0;n2<8;n2++) r[n2] = s[L*SW + nidx(v + 16*n2)];
    fft128<1>(r, s, L, v);
    #pragma unroll
    for(int j=0;j<8;j++){ int i=k2+8*j+64*t1; s[L*SW+nidx(i)] = r[j]; }
    __syncthreads();
    #pragma unroll
    for(int k=0;k<8;k++){ int e=tid+k*256; int i=e>>4, l=e&15;
        outZ[base + l + i*M2] = s[l*SW+nidx(i)]; }
}

// ---------------------------------------------------------------------------
__global__ void zero_kernel(float4* __restrict__ r){
    r[blockIdx.x*256 + threadIdx.x] = make_float4(0.f,0.f,0.f,0.f);
}

__global__ void paint_kernel(const float* __restrict__ pos,
                             float* __restrict__ grid, int N){
    int n = blockIdx.x*256 + threadIdx.x;
    if (n >= N) return;
    float px = pos[3*n+0], py = pos[3*n+1], pz = pos[3*n+2];
    float f0x = floorf(px), f0y = floorf(py), f0z = floorf(pz);
    int ix = ((int)f0x)&127, iy = ((int)f0y)&127, iz = ((int)f0z)&127;
    float dx = px-f0x, dy = py-f0y, dz = pz-f0z;
    float wx[2]={1.f-dx,dx}, wy[2]={1.f-dy,dy};
    float wz0 = 1.f-dz, wz1 = dz;
    int xi[2]={ix,(ix+1)&127}, yi[2]={iy,(iy+1)&127};
    bool aligned = (iz & 1) == 0;     // even iz: (iz, iz+1) is an aligned float2
    int iz1 = (iz + 1) & 127;
#pragma unroll
    for(int a=0;a<2;a++)
#pragma unroll
    for(int b=0;b<2;b++){
        float wab = wx[a]*wy[b];
        int rowbase = xi[a]*M2 + yi[b]*MESHN;
        if (aligned){
            atomicAdd((float2*)(grid + rowbase + iz),
                      make_float2(wab*wz0, wab*wz1));
        } else {
            atomicAdd(grid + rowbase + iz,  wab*wz0);
            atomicAdd(grid + rowbase + iz1, wab*wz1);
        }
    }
}

__global__ void gather_kernel(const float* __restrict__ pos,
                              const float* __restrict__ vel,
                              const float* __restrict__ drift,
                              const float4* __restrict__ G,
                              float* __restrict__ out, int N){
    int n = blockIdx.x*256 + threadIdx.x;
    if (n >= N) return;
    float px = pos[3*n+0], py = pos[3*n+1], pz = pos[3*n+2];
    float f0x = floorf(px), f0y = floorf(py), f0z = floorf(pz);
    int ix = ((int)f0x)&127, iy = ((int)f0y)&127, iz = ((int)f0z)&127;
    float dx = px-f0x, dy = py-f0y, dz = pz-f0z;
    float wx[2]={1.f-dx,dx}, wy[2]={1.f-dy,dy}, wz[2]={1.f-dz,dz};
    int xi[2]={ix,(ix+1)&127}, yi[2]={iy,(iy+1)&127}, zi[2]={iz,(iz+1)&127};
    float fx=0.f, fy=0.f, fzv=0.f;
#pragma unroll
    for(int a=0;a<2;a++)
#pragma unroll
    for(int b=0;b<2;b++)
#pragma unroll
    for(int c=0;c<2;c++){
        float4 v4 = G[xi[a]*M2 + yi[b]*MESHN + zi[c]];
        float w = wx[a]*wy[b]*wz[c];
        fx += w*v4.x; fy += w*v4.y; fzv += w*v4.z;
    }
    float sc = 0.2f / drift[0];
    out[3*n+0]=px; out[3*n+1]=py; out[3*n+2]=pz;
    float* ov = out + (size_t)3*N;
    ov[3*n+0]=vel[3*n+0]+fx*sc;
    ov[3*n+1]=vel[3*n+1]+fy*sc;
    ov[3*n+2]=vel[3*n+2]+fzv*sc;
}

// ---------------------------------------------------------------------------
extern "C" void kernel_launch(void* const* d_in, const int* in_sizes, int n_in,
                              void* d_out, int out_size){
    const float* pos   = (const float*)d_in[0];
    const float* vel   = (const float*)d_in[1];
    const float* drift = (const float*)d_in[2];
    float* out = (float*)d_out;
    int N = in_sizes[0] / 3;

    void *pR,*pA,*pB,*pC,*pG;
    cudaGetSymbolAddress(&pR, g_real);
    cudaGetSymbolAddress(&pA, g_A);
    cudaGetSymbolAddress(&pB, g_B);
    cudaGetSymbolAddress(&pC, g_C);
    cudaGetSymbolAddress(&pG, g_G);
    float*  R = (float*)pR;
    float2* A = (float2*)pA;
    float2* B = (float2*)pB;
    float2* C = (float2*)pC;
    float4* G = (float4*)pG;

    cudaFuncSetAttribute(fft_plane_fwd, cudaFuncAttributeMaxDynamicSharedMemorySize, SMEM_PLANE);
    cudaFuncSetAttribute(fft_plane_inv, cudaFuncAttributeMaxDynamicSharedMemorySize, SMEM_PLANE);

    // 1. zero + CIC paint
    zero_kernel<<<M3/1024, 256>>>((float4*)R);
    paint_kernel<<<(N+255)/256, 256>>>(pos, R, N);

    // 2. forward z+y (per-x plane): R -> B
    fft_plane_fwd<<<128, 1024, SMEM_PLANE>>>(R, B);

    // 3. fused x: fwd + filter + x-inv(Fxy)->A, x-inv(Fz)->C
    fft_x_fused<<<1024, 256>>>(B, A, C);

    // 4. inverse y+z planes (Fz then Fxy per plane) -> G (float4, coalesced)
    fft_plane_inv<<<128, 1024, SMEM_PLANE>>>(A, C, G);

    // 5. CIC gather + velocity boost
    gather_kernel<<<(N+255)/256, 256>>>(pos, vel, drift, G, out, N);
}

// round 5
// speedup vs baseline: 2.1875x; 1.0239x over previous
#include <cuda_runtime.h>
#include <math.h>

#define MESHN 128
#define M2    16384
#define M3    2097152
#define SW    145    // fft128 transpose scratch line stride (float2)
#define PST   137    // plane row stride (float2)

// Scratch (static device globals — no runtime allocation)
__device__ float  g_real[M3];
__device__ float2 g_A[M3];
__device__ float2 g_B[M3];
__device__ float2 g_C[M3];
__device__ float4 g_G[M3];

// ---------------------------------------------------------------------------
__device__ __forceinline__ float2 cadd(float2 a, float2 b){ return make_float2(a.x+b.x, a.y+b.y); }
__device__ __forceinline__ float2 csub(float2 a, float2 b){ return make_float2(a.x-b.x, a.y-b.y); }
__device__ __forceinline__ float2 cmul(float2 a, float2 b){ return make_float2(a.x*b.x-a.y*b.y, a.x*b.y+a.y*b.x); }
template<int SGN>
__device__ __forceinline__ float2 cmulJ(float2 a){ return make_float2((float)(-SGN)*a.y, (float)SGN*a.x); }

// padded index: +8 after each 64 (bank de-conflict)
__device__ __forceinline__ int nidx(int i){ return i + ((i>>6)<<3); }
__device__ __forceinline__ int pidx(int e){ return nidx(e>>7)*PST + nidx(e&127); }

template<int SGN>
__device__ __forceinline__ void dft8(float2* a){
    const float R2 = 0.70710678118654752f;
    const float2 W1 = make_float2( R2, (float)SGN*R2);
    const float2 W3 = make_float2(-R2, (float)SGN*R2);
    float2 t0=cadd(a[0],a[4]), t4=csub(a[0],a[4]);
    float2 t1=cadd(a[1],a[5]), t5=cmul(csub(a[1],a[5]),W1);
    float2 t2=cadd(a[2],a[6]), t6=cmulJ<SGN>(csub(a[2],a[6]));
    float2 t3=cadd(a[3],a[7]), t7=cmul(csub(a[3],a[7]),W3);
    float2 u0=cadd(t0,t2), u2=csub(t0,t2);
    float2 u1=cadd(t1,t3), u3=cmulJ<SGN>(csub(t1,t3));
    a[0]=cadd(u0,u1); a[4]=csub(u0,u1);
    a[2]=cadd(u2,u3); a[6]=csub(u2,u3);
    float2 v0=cadd(t4,t6), v2=csub(t4,t6);
    float2 v1=cadd(t5,t7), v3=cmulJ<SGN>(csub(t5,t7));
    a[1]=cadd(v0,v1); a[5]=csub(v0,v1);
    a[3]=cadd(v2,v3); a[7]=csub(v2,v3);
}

// 128-pt FFT: 16 threads/line (same warp), 8 regs/thread.
// In: r[n2]=x[v+16n2]. Out: r[j]=X[k2+8j+64t1], k2=v>>1, t1=v&1.
// w = exp(SGN*i*2*pi*v/128) precomputed by caller.
// Scratch line L is private to this line's 16 threads -> WARP-scope sync only.
template<int SGN>
__device__ __forceinline__ void fft128(float2* r, float2* s, int L, int v, float2 w){
    __syncwarp();                          // scratch reuse guard (warp-local)
    dft8<SGN>(r);
    float2 t = w;
    #pragma unroll
    for(int k2=1;k2<8;k2++){ r[k2]=cmul(r[k2],t); t=cmul(t,w); }
    float2* sl = s + L*SW;
    #pragma unroll
    for(int k2=0;k2<8;k2++) sl[k2*18 + v] = r[k2];
    __syncwarp();
    int k2 = v>>1, t1 = v&1;
    #pragma unroll
    for(int q=0;q<8;q++) r[q] = sl[k2*18 + t1 + 2*q];
    __syncwarp();
    dft8<SGN>(r);
    if (t1){
        const float2 w16 = make_float2(0.92387953251128674f, (float)SGN*0.38268343236508977f);
        float2 tt = w16;
        #pragma unroll
        for(int j=1;j<8;j++){ r[j]=cmul(r[j],tt); tt=cmul(tt,w16); }
    }
    #pragma unroll
    for(int j=0;j<8;j++){
        float px = __shfl_xor_sync(0xFFFFFFFFu, r[j].x, 1);
        float py = __shfl_xor_sync(0xFFFFFFFFu, r[j].y, 1);
        if (t1==0) r[j] = make_float2(r[j].x+px, r[j].y+py);
        else       r[j] = make_float2(px-r[j].x, py-r[j].y);
    }
}

__device__ __forceinline__ float2 twiddle_v(int SGN, int v){
    float sa, ca;
    __sincosf((float)SGN * 0.049087385212340526f * (float)v, &sa, &ca);
    return make_float2(ca, sa);
}

// ---------------------------------------------------------------------------
// In-smem 2D FFT of a 128x128 plane. 1024 threads = 64 concurrent lines,
// 2 iterations per axis. z-axis (stride 1) then y-axis (stride PST).
// Block-wide syncs only at cross-warp plane exchanges.
template<int SGN>
__device__ __forceinline__ void plane_fft2d(float2* plane, float2* scratch, float2 w){
    int tid=threadIdx.x, L=tid>>4, v=tid&15, k2=v>>1, t1=v&1;
    float2 r[8];
    // z-axis: rows are line-local (16 threads own a full row) -> no block sync
    #pragma unroll
    for(int it=0; it<2; it++){
        float2* row = plane + nidx(it*64+L)*PST;
        #pragma unroll
        for(int n2=0;n2<8;n2++) r[n2]=row[nidx(v+16*n2)];
        fft128<SGN>(r, scratch, L, v, w);
        #pragma unroll
        for(int j=0;j<8;j++) row[nidx(k2+8*j+64*t1)]=r[j];
    }
    __syncthreads();   // cross-warp: y-phase reads all rows
    #pragma unroll
    for(int it=0; it<2; it++){
        int zc = nidx(it*64+L);
        #pragma unroll
        for(int n2=0;n2<8;n2++) r[n2]=plane[nidx(v+16*n2)*PST + zc];
        fft128<SGN>(r, scratch, L, v, w);
        #pragma unroll
        for(int j=0;j<8;j++) plane[nidx(k2+8*j+64*t1)*PST + zc]=r[j];
    }
    __syncthreads();   // cross-warp: caller reads full plane
}

#define PLANE_F2   (136*PST)                 // 18,632 float2
#define SMEM_PLANE ((PLANE_F2 + 64*SW)*8)    // 223,296 bytes

// Forward: real grid plane -> 2D FFT (z,y) -> complex out. grid.x = 128 (x).
__global__ void __launch_bounds__(1024, 1)
fft_plane_fwd(const float* __restrict__ rin, float2* __restrict__ out){
    extern __shared__ float2 sm[];
    float2* plane = sm; float2* scratch = sm + PLANE_F2;
    int tid = threadIdx.x;
    float2 w = twiddle_v(-1, tid&15);
    size_t base = (size_t)blockIdx.x * M2;
    #pragma unroll
    for(int k=0;k<16;k++){
        int e = tid + k*1024;
        plane[pidx(e)] = make_float2(rin[base+e], 0.f);
    }
    __syncthreads();
    plane_fft2d<-1>(plane, scratch, w);
    #pragma unroll
    for(int k=0;k<16;k++){
        int e = tid + k*1024;
        out[base+e] = plane[pidx(e)];
    }
}

// Combined inverse: per x-plane, Fz plane FFT (real parts -> regs), then Fxy
// plane FFT, then one coalesced float4 store. 128 blocks = exactly one wave.
__global__ void __launch_bounds__(1024, 1)
fft_plane_inv(const float2* __restrict__ inXY, const float2* __restrict__ inZ,
              float4* __restrict__ G){
    extern __shared__ float2 sm[];
    float2* plane = sm; float2* scratch = sm + PLANE_F2;
    int tid = threadIdx.x;
    float2 w = twiddle_v(1, tid&15);
    size_t base = (size_t)blockIdx.x * M2;

    // --- Fz plane ---
    #pragma unroll
    for(int k=0;k<16;k++){
        int e = tid + k*1024;
        plane[pidx(e)] = inZ[base+e];
    }
    __syncthreads();
    plane_fft2d<1>(plane, scratch, w);
    float zreg[16];
    #pragma unroll
    for(int k=0;k<16;k++){
        int e = tid + k*1024;
        zreg[k] = plane[pidx(e)].x;       // same-thread read...
        plane[pidx(e)] = inXY[base+e];    // ...then same-thread overwrite: no race
    }
    __syncthreads();

    // --- Fxy plane ---
    plane_fft2d<1>(plane, scratch, w);
    #pragma unroll
    for(int k=0;k<16;k++){
        int e = tid + k*1024;
        float2 xy = plane[pidx(e)];
        G[base+e] = make_float4(xy.x, xy.y, zreg[k], 0.f);
    }
}

// ---------------------------------------------------------------------------
// Fused x-axis: fwd FFT -> spectral filter -> inverse FFT (Fxy) -> inverse (Fz)
__global__ void __launch_bounds__(256)
fft_x_fused(const float2* __restrict__ in, float2* __restrict__ outXY,
            float2* __restrict__ outZ){
    __shared__ float2 s[16*SW];
    int tid=threadIdx.x, L=tid>>4, v=tid&15;
    float2 wf = twiddle_v(-1, v);
    float2 wi = twiddle_v( 1, v);
    int base = blockIdx.x*16;
    float2 r[8];
    #pragma unroll
    for(int k=0;k<8;k++){ int e=tid+k*256; int i=e>>4, l=e&15;
        s[l*SW+nidx(i)] = in[base + l + i*M2]; }
    __syncthreads();
    #pragma unroll
    for(int n2=0;n2<8;n2++) r[n2] = s[L*SW + nidx(v + 16*n2)];
    fft128<-1>(r, s, L, v, wf);

    int k2=v>>1, t1=v&1;
    int ylz = base + L;
    int y = ylz>>7, z = ylz&127;
    const float ku = 0.049087385212340526f;
    float ky = (float)((y<64)?y:y-128)*ku;
    float kz = (float)((z<64)?z:z-128)*ku;
    float kyz2 = ky*ky + kz*kz;
    float2 fz[8];
    #pragma unroll
    for(int j=0;j<8;j++){
        int i = k2+8*j+64*t1;
        float kx = (float)((i<64)?i:i-128)*ku;
        float kk = kx*kx + kyz2;
        float coef = 0.f;
        if (kk > 0.f){
            float ikk = 1.f/kk;
            coef = -ikk * __expf(-0.09f*ikk - kk*kk) * (1.f/2097152.f);
        }
        float pr = r[j].x*coef, pi = r[j].y*coef;
        r[j]  = make_float2(pr*ky + pi*kx, pi*ky - pr*kx);
        fz[j] = make_float2(pi*kz, -pr*kz);
    }

    // inverse x on Fxy (all smem traffic line-local -> warp sync inside fft128)
    #pragma unroll
    for(int j=0;j<8;j++){ int i=k2+8*j+64*t1; s[L*SW+nidx(i)] = r[j]; }
    __syncwarp();
    #pragma unroll
    for(int n2=0;n2<8;n2++) r[n2] = s[L*SW + nidx(v + 16*n2)];
    fft128<1>(r, s, L, v, wi);
    #pragma unroll
    for(int j=0;j<8;j++){ int i=k2+8*j+64*t1; s[L*SW+nidx(i)] = r[j]; }
    __syncthreads();     // cross-warp: coalesced global store reads mixed lines
    #pragma unroll
    for(int k=0;k<8;k++){ int e=tid+k*256; int i=e>>4, l=e&15;
        outXY[base + l + i*M2] = s[l*SW+nidx(i)]; }
    __syncthreads();     // cross-warp: smem about to be overwritten per-line

    #pragma unroll
    for(int j=0;j<8;j++){ int i=k2+8*j+64*t1; s[L*SW+nidx(i)] = fz[j]; }
    __syncwarp();
    #pragma unroll
    for(int n2=0;n2<8;n2++) r[n2] = s[L*SW + nidx(v + 16*n2)];
    fft128<1>(r, s, L, v, wi);
    #pragma unroll
    for(int j=0;j<8;j++){ int i=k2+8*j+64*t1; s[L*SW+nidx(i)] = r[j]; }
    __syncthreads();
    #pragma unroll
    for(int k=0;k<8;k++){ int e=tid+k*256; int i=e>>4, l=e&15;
        outZ[base + l + i*M2] = s[l*SW+nidx(i)]; }
}

// ---------------------------------------------------------------------------
__global__ void zero_kernel(float4* __restrict__ r){
    r[blockIdx.x*256 + threadIdx.x] = make_float4(0.f,0.f,0.f,0.f);
}

__global__ void paint_kernel(const float* __restrict__ pos,
                             float* __restrict__ grid, int N){
    int n = blockIdx.x*256 + threadIdx.x;
    if (n >= N) return;
    float px = pos[3*n+0], py = pos[3*n+1], pz = pos[3*n+2];
    float f0x = floorf(px), f0y = floorf(py), f0z = floorf(pz);
    int ix = ((int)f0x)&127, iy = ((int)f0y)&127, iz = ((int)f0z)&127;
    float dx = px-f0x, dy = py-f0y, dz = pz-f0z;
    float wx[2]={1.f-dx,dx}, wy[2]={1.f-dy,dy};
    float wz0 = 1.f-dz, wz1 = dz;
    int xi[2]={ix,(ix+1)&127}, yi[2]={iy,(iy+1)&127};
    bool aligned = (iz & 1) == 0;
    int iz1 = (iz + 1) & 127;
#pragma unroll
    for(int a=0;a<2;a++)
#pragma unroll
    for(int b=0;b<2;b++){
        float wab = wx[a]*wy[b];
        int rowbase = xi[a]*M2 + yi[b]*MESHN;
        if (aligned){
            atomicAdd((float2*)(grid + rowbase + iz),
                      make_float2(wab*wz0, wab*wz1));
        } else {
            atomicAdd(grid + rowbase + iz,  wab*wz0);
            atomicAdd(grid + rowbase + iz1, wab*wz1);
        }
    }
}

__global__ void gather_kernel(const float* __restrict__ pos,
                              const float* __restrict__ vel,
                              const float* __restrict__ drift,
                              const float4* __restrict__ G,
                              float* __restrict__ out, int N){
    int n = blockIdx.x*256 + threadIdx.x;
    if (n >= N) return;
    float px = pos[3*n+0], py = pos[3*n+1], pz = pos[3*n+2];
    float f0x = floorf(px), f0y = floorf(py), f0z = floorf(pz);
    int ix = ((int)f0x)&127, iy = ((int)f0y)&127, iz = ((int)f0z)&127;
    float dx = px-f0x, dy = py-f0y, dz = pz-f0z;
    float wx[2]={1.f-dx,dx}, wy[2]={1.f-dy,dy}, wz[2]={1.f-dz,dz};
    int xi[2]={ix,(ix+1)&127}, yi[2]={iy,(iy+1)&127}, zi[2]={iz,(iz+1)&127};
    float fx=0.f, fy=0.f, fzv=0.f;
#pragma unroll
    for(int a=0;a<2;a++)
#pragma unroll
    for(int b=0;b<2;b++)
#pragma unroll
    for(int c=0;c<2;c++){
        float4 v4 = G[xi[a]*M2 + yi[b]*MESHN + zi[c]];
        float w = wx[a]*wy[b]*wz[c];
        fx += w*v4.x; fy += w*v4.y; fzv += w*v4.z;
    }
    float sc = 0.2f / drift[0];
    out[3*n+0]=px; out[3*n+1]=py; out[3*n+2]=pz;
    float* ov = out + (size_t)3*N;
    ov[3*n+0]=vel[3*n+0]+fx*sc;
    ov[3*n+1]=vel[3*n+1]+fy*sc;
    ov[3*n+2]=vel[3*n+2]+fzv*sc;
}

// ---------------------------------------------------------------------------
extern "C" void kernel_launch(void* const* d_in, const int* in_sizes, int n_in,
                              void* d_out, int out_size){
    const float* pos   = (const float*)d_in[0];
    const float* vel   = (const float*)d_in[1];
    const float* drift = (const float*)d_in[2];
    float* out = (float*)d_out;
    int N = in_sizes[0] / 3;

    void *pR,*pA,*pB,*pC,*pG;
    cudaGetSymbolAddress(&pR, g_real);
    cudaGetSymbolAddress(&pA, g_A);
    cudaGetSymbolAddress(&pB, g_B);
    cudaGetSymbolAddress(&pC, g_C);
    cudaGetSymbolAddress(&pG, g_G);
    float*  R = (float*)pR;
    float2* A = (float2*)pA;
    float2* B = (float2*)pB;
    float2* C = (float2*)pC;
    float4* G = (float4*)pG;

    cudaFuncSetAttribute(fft_plane_fwd, cudaFuncAttributeMaxDynamicSharedMemorySize, SMEM_PLANE);
    cudaFuncSetAttribute(fft_plane_inv, cudaFuncAttributeMaxDynamicSharedMemorySize, SMEM_PLANE);

    // 1. zero + CIC paint
    zero_kernel<<<M3/1024, 256>>>((float4*)R);
    paint_kernel<<<(N+255)/256, 256>>>(pos, R, N);

    // 2. forward z+y (per-x plane): R -> B
    fft_plane_fwd<<<128, 1024, SMEM_PLANE>>>(R, B);

    // 3. fused x: fwd + filter + x-inv(Fxy)->A, x-inv(Fz)->C
    fft_x_fused<<<1024, 256>>>(B, A, C);

    // 4. inverse y+z planes (Fz then Fxy per plane) -> G (float4, coalesced)
    fft_plane_inv<<<128, 1024, SMEM_PLANE>>>(A, C, G);

    // 5. CIC gather + velocity boost
    gather_kernel<<<(N+255)/256, 256>>>(pos, vel, drift, G, out, N);
}

// round 6
// speedup vs baseline: 2.3792x; 1.0876x over previous
#include <cuda_runtime.h>
#include <math.h>

#define MESHN 128
#define M2    16384
#define M3    2097152
#define SW    145    // fft128 transpose scratch line stride (float2)
#define PST   137    // plane row stride (float2)
#define RR    1764   // spectral ball radius^2 (42^2): filter < 3e-8 outside

// Scratch (static device globals — zero-initialized, no runtime allocation)
__device__ float  g_real[M3];
__device__ float2 g_A[M3];
__device__ float2 g_B[M3];
__device__ float2 g_C[M3];
__device__ float4 g_G[M3];

// ---------------------------------------------------------------------------
__device__ __forceinline__ float2 cadd(float2 a, float2 b){ return make_float2(a.x+b.x, a.y+b.y); }
__device__ __forceinline__ float2 csub(float2 a, float2 b){ return make_float2(a.x-b.x, a.y-b.y); }
__device__ __forceinline__ float2 cmul(float2 a, float2 b){ return make_float2(a.x*b.x-a.y*b.y, a.x*b.y+a.y*b.x); }
template<int SGN>
__device__ __forceinline__ float2 cmulJ(float2 a){ return make_float2((float)(-SGN)*a.y, (float)SGN*a.x); }

// padded index: +8 after each 64 (bank de-conflict)
__device__ __forceinline__ int nidx(int i){ return i + ((i>>6)<<3); }
__device__ __forceinline__ int pidx(int e){ return nidx(e>>7)*PST + nidx(e&127); }

template<int SGN>
__device__ __forceinline__ void dft8(float2* a){
    const float R2 = 0.70710678118654752f;
    const float2 W1 = make_float2( R2, (float)SGN*R2);
    const float2 W3 = make_float2(-R2, (float)SGN*R2);
    float2 t0=cadd(a[0],a[4]), t4=csub(a[0],a[4]);
    float2 t1=cadd(a[1],a[5]), t5=cmul(csub(a[1],a[5]),W1);
    float2 t2=cadd(a[2],a[6]), t6=cmulJ<SGN>(csub(a[2],a[6]));
    float2 t3=cadd(a[3],a[7]), t7=cmul(csub(a[3],a[7]),W3);
    float2 u0=cadd(t0,t2), u2=csub(t0,t2);
    float2 u1=cadd(t1,t3), u3=cmulJ<SGN>(csub(t1,t3));
    a[0]=cadd(u0,u1); a[4]=csub(u0,u1);
    a[2]=cadd(u2,u3); a[6]=csub(u2,u3);
    float2 v0=cadd(t4,t6), v2=csub(t4,t6);
    float2 v1=cadd(t5,t7), v3=cmulJ<SGN>(csub(t5,t7));
    a[1]=cadd(v0,v1); a[5]=csub(v0,v1);
    a[3]=cadd(v2,v3); a[7]=csub(v2,v3);
}

// 128-pt FFT: 16 threads/line (same warp), 8 regs/thread.
// In: r[n2]=x[v+16n2]. Out: r[j]=X[k2+8j+64t1], k2=v>>1, t1=v&1.
// Scratch line L private to line's 16 threads -> warp-scope sync only.
template<int SGN>
__device__ __forceinline__ void fft128(float2* r, float2* s, int L, int v, float2 w){
    __syncwarp();
    dft8<SGN>(r);
    float2 t = w;
    #pragma unroll
    for(int k2=1;k2<8;k2++){ r[k2]=cmul(r[k2],t); t=cmul(t,w); }
    float2* sl = s + L*SW;
    #pragma unroll
    for(int k2=0;k2<8;k2++) sl[k2*18 + v] = r[k2];
    __syncwarp();
    int k2 = v>>1, t1 = v&1;
    #pragma unroll
    for(int q=0;q<8;q++) r[q] = sl[k2*18 + t1 + 2*q];
    __syncwarp();
    dft8<SGN>(r);
    if (t1){
        const float2 w16 = make_float2(0.92387953251128674f, (float)SGN*0.38268343236508977f);
        float2 tt = w16;
        #pragma unroll
        for(int j=1;j<8;j++){ r[j]=cmul(r[j],tt); tt=cmul(tt,w16); }
    }
    #pragma unroll
    for(int j=0;j<8;j++){
        float px = __shfl_xor_sync(0xFFFFFFFFu, r[j].x, 1);
        float py = __shfl_xor_sync(0xFFFFFFFFu, r[j].y, 1);
        if (t1==0) r[j] = make_float2(r[j].x+px, r[j].y+py);
        else       r[j] = make_float2(px-r[j].x, py-r[j].y);
    }
}

__device__ __forceinline__ float2 twiddle_v(int SGN, int v){
    float sa, ca;
    __sincosf((float)SGN * 0.049087385212340526f * (float)v, &sa, &ca);
    return make_float2(ca, sa);
}

// ---------------------------------------------------------------------------
// In-smem 2D FFT of a 128x128 plane. 1024 threads = 64 concurrent lines.
// Phase 1: contiguous axis (rows). Phase 2: strided axis (columns).
// PRUNE: 0 = none; 1 = skip phase-1 row warps with |m_row|>41 (inverse, rows=ky
// are exact zeros outside the spectral ball); 2 = skip phase-2 column warps
// with |m_col|>41 (forward, those kz columns feed only filtered-out modes).
template<int SGN, int PRUNE>
__device__ __forceinline__ void plane_fft2d(float2* plane, float2* scratch, float2 w){
    int tid=threadIdx.x, L=tid>>4, v=tid&15, k2=v>>1, t1=v&1;
    float2 r[8];
    #pragma unroll
    for(int it=0; it<2; it++){
        bool act = true;
        if (PRUNE==1){
            int p0 = it*64 + (L & ~1);            // warp's first row
            int minabs = (p0 < 64) ? p0 : 127 - p0;
            act = (minabs <= 41);
        }
        if (act){
            float2* row = plane + nidx(it*64+L)*PST;
            #pragma unroll
            for(int n2=0;n2<8;n2++) r[n2]=row[nidx(v+16*n2)];
            fft128<SGN>(r, scratch, L, v, w);
            #pragma unroll
            for(int j=0;j<8;j++) row[nidx(k2+8*j+64*t1)]=r[j];
        }
    }
    __syncthreads();
    #pragma unroll
    for(int it=0; it<2; it++){
        bool act = true;
        if (PRUNE==2){
            int p0 = it*64 + (L & ~1);            // warp's first column
            int minabs = (p0 < 64) ? p0 : 127 - p0;
            act = (minabs <= 41);
        }
        if (act){
            int zc = nidx(it*64+L);
            #pragma unroll
            for(int n2=0;n2<8;n2++) r[n2]=plane[nidx(v+16*n2)*PST + zc];
            fft128<SGN>(r, scratch, L, v, w);
            #pragma unroll
            for(int j=0;j<8;j++) plane[nidx(k2+8*j+64*t1)*PST + zc]=r[j];
        }
    }
    __syncthreads();
}

#define PLANE_F2   (136*PST)                 // 18,632 float2
#define SMEM_PLANE ((PLANE_F2 + 64*SW)*8)    // 223,296 bytes

// Forward: real grid plane -> 2D FFT (z,y) -> complex out. grid.x = 128 (x).
__global__ void __launch_bounds__(1024, 1)
fft_plane_fwd(const float* __restrict__ rin, float2* __restrict__ out){
    extern __shared__ float2 sm[];
    float2* plane = sm; float2* scratch = sm + PLANE_F2;
    int tid = threadIdx.x;
    float2 w = twiddle_v(-1, tid&15);
    size_t base = (size_t)blockIdx.x * M2;
    #pragma unroll
    for(int k=0;k<16;k++){
        int e = tid + k*1024;
        plane[pidx(e)] = make_float2(rin[base+e], 0.f);
    }
    __syncthreads();
    plane_fft2d<-1,2>(plane, scratch, w);       // prune y-phase cols |m_kz|>41
    #pragma unroll
    for(int k=0;k<16;k++){
        int e = tid + k*1024;
        out[base+e] = plane[pidx(e)];
    }
}

// Combined inverse: per x-plane, Fz plane FFT (real parts -> regs), then Fxy
// plane FFT, then one coalesced float4 store. 128 blocks = exactly one wave.
__global__ void __launch_bounds__(1024, 1)
fft_plane_inv(const float2* __restrict__ inXY, const float2* __restrict__ inZ,
              float4* __restrict__ G){
    extern __shared__ float2 sm[];
    float2* plane = sm; float2* scratch = sm + PLANE_F2;
    int tid = threadIdx.x;
    float2 w = twiddle_v(1, tid&15);
    size_t base = (size_t)blockIdx.x * M2;

    // --- Fz plane ---
    #pragma unroll
    for(int k=0;k<16;k++){
        int e = tid + k*1024;
        plane[pidx(e)] = inZ[base+e];
    }
    __syncthreads();
    plane_fft2d<1,1>(plane, scratch, w);        // prune kz-rows |m_ky|>41 (exact zeros)
    float zreg[16];
    #pragma unroll
    for(int k=0;k<16;k++){
        int e = tid + k*1024;
        zreg[k] = plane[pidx(e)].x;       // same-thread read...
        plane[pidx(e)] = inXY[base+e];    // ...then same-thread overwrite: no race
    }
    __syncthreads();

    // --- Fxy plane ---
    plane_fft2d<1,1>(plane, scratch, w);
    #pragma unroll
    for(int k=0;k<16;k++){
        int e = tid + k*1024;
        float2 xy = plane[pidx(e)];
        G[base+e] = make_float4(xy.x, xy.y, zreg[k], 0.f);
    }
}

// ---------------------------------------------------------------------------
// Fused x-axis: fwd FFT -> spectral filter -> inverse FFT (Fxy) -> inverse (Fz)
// Early-exits blocks entirely outside the spectral ball (outputs stay zero).
__global__ void __launch_bounds__(256)
fft_x_fused(const float2* __restrict__ in, float2* __restrict__ outXY,
            float2* __restrict__ outZ){
    __shared__ float2 s[16*SW];
    int base = blockIdx.x*16;
    {   // spectral-ball block cull: all 16 lines share y; z spans [z0, z0+16)
        int y  = base >> 7;
        int z0 = base & 127;
        int my = (y  < 64) ? y  : 128 - y;
        int mz = (z0 < 64) ? z0 : 113 - z0;   // min |mz| over the 16-z group
        if (my*my + mz*mz > RR) return;
    }
    int tid=threadIdx.x, L=tid>>4, v=tid&15;
    float2 wf = twiddle_v(-1, v);
    float2 wi = twiddle_v( 1, v);
    float2 r[8];
    #pragma unroll
    for(int k=0;k<8;k++){ int e=tid+k*256; int i=e>>4, l=e&15;
        s[l*SW+nidx(i)] = in[base + l + i*M2]; }
    __syncthreads();
    #pragma unroll
    for(int n2=0;n2<8;n2++) r[n2] = s[L*SW + nidx(v + 16*n2)];
    fft128<-1>(r, s, L, v, wf);

    int k2=v>>1, t1=v&1;
    int ylz = base + L;
    int y = ylz>>7, z = ylz&127;
    const float ku = 0.049087385212340526f;
    float ky = (float)((y<64)?y:y-128)*ku;
    float kz = (float)((z<64)?z:z-128)*ku;
    float kyz2 = ky*ky + kz*kz;
    float2 fz[8];
    #pragma unroll
    for(int j=0;j<8;j++){
        int i = k2+8*j+64*t1;
        float kx = (float)((i<64)?i:i-128)*ku;
        float kk = kx*kx + kyz2;
        float coef = 0.f;
        if (kk > 0.f){
            float ikk = 1.f/kk;
            coef = -ikk * __expf(-0.09f*ikk - kk*kk) * (1.f/2097152.f);
        }
        float pr = r[j].x*coef, pi = r[j].y*coef;
        r[j]  = make_float2(pr*ky + pi*kx, pi*ky - pr*kx);
        fz[j] = make_float2(pi*kz, -pr*kz);
    }

    // inverse x on Fxy (all smem traffic line-local -> warp sync inside fft128)
    #pragma unroll
    for(int j=0;j<8;j++){ int i=k2+8*j+64*t1; s[L*SW+nidx(i)] = r[j]; }
    __syncwarp();
    #pragma unroll
    for(int n2=0;n2<8;n2++) r[n2] = s[L*SW + nidx(v + 16*n2)];
    fft128<1>(r, s, L, v, wi);
    #pragma unroll
    for(int j=0;j<8;j++){ int i=k2+8*j+64*t1; s[L*SW+nidx(i)] = r[j]; }
    __syncthreads();     // cross-warp: coalesced global store reads mixed lines
    #pragma unroll
    for(int k=0;k<8;k++){ int e=tid+k*256; int i=e>>4, l=e&15;
        outXY[base + l + i*M2] = s[l*SW+nidx(i)]; }
    __syncthreads();     // cross-warp: smem about to be overwritten per-line

    #pragma unroll
    for(int j=0;j<8;j++){ int i=k2+8*j+64*t1; s[L*SW+nidx(i)] = fz[j]; }
    __syncwarp();
    #pragma unroll
    for(int n2=0;n2<8;n2++) r[n2] = s[L*SW + nidx(v + 16*n2)];
    fft128<1>(r, s, L, v, wi);
    #pragma unroll
    for(int j=0;j<8;j++){ int i=k2+8*j+64*t1; s[L*SW+nidx(i)] = r[j]; }
    __syncthreads();
    #pragma unroll
    for(int k=0;k<8;k++){ int e=tid+k*256; int i=e>>4, l=e&15;
        outZ[base + l + i*M2] = s[l*SW+nidx(i)]; }
}

// ---------------------------------------------------------------------------
__global__ void zero_kernel(float4* __restrict__ r){
    r[blockIdx.x*256 + threadIdx.x] = make_float4(0.f,0.f,0.f,0.f);
}

__global__ void paint_kernel(const float* __restrict__ pos,
                             float* __restrict__ grid, int N){
    int n = blockIdx.x*256 + threadIdx.x;
    if (n >= N) return;
    float px = pos[3*n+0], py = pos[3*n+1], pz = pos[3*n+2];
    float f0x = floorf(px), f0y = floorf(py), f0z = floorf(pz);
    int ix = ((int)f0x)&127, iy = ((int)f0y)&127, iz = ((int)f0z)&127;
    float dx = px-f0x, dy = py-f0y, dz = pz-f0z;
    float wx[2]={1.f-dx,dx}, wy[2]={1.f-dy,dy};
    float wz0 = 1.f-dz, wz1 = dz;
    int xi[2]={ix,(ix+1)&127}, yi[2]={iy,(iy+1)&127};
    int lanez = iz & 3;
    int zb = iz & ~3;
    int iz1 = (iz + 1) & 127;
    if (lanez < 3){
        // both z-corners inside one aligned 16B block -> single vector RED
        float v0=0.f, v1=0.f, v2=0.f, v3=0.f;
        if      (lanez == 0){ v0=wz0; v1=wz1; }
        else if (lanez == 1){ v1=wz0; v2=wz1; }
        else                { v2=wz0; v3=wz1; }
#pragma unroll
        for(int a=0;a<2;a++)
#pragma unroll
        for(int b=0;b<2;b++){
            float wab = wx[a]*wy[b];
            atomicAdd((float4*)(grid + xi[a]*M2 + yi[b]*MESHN + zb),
                      make_float4(wab*v0, wab*v1, wab*v2, wab*v3));
        }
    } else {
#pragma unroll
        for(int a=0;a<2;a++)
#pragma unroll
        for(int b=0;b<2;b++){
            float wab = wx[a]*wy[b];
            int rowbase = xi[a]*M2 + yi[b]*MESHN;
            atomicAdd(grid + rowbase + iz,  wab*wz0);
            atomicAdd(grid + rowbase + iz1, wab*wz1);
        }
    }
}

__global__ void gather_kernel(const float* __restrict__ pos,
                              const float* __restrict__ vel,
                              const float* __restrict__ drift,
                              const float4* __restrict__ G,
                              float* __restrict__ out, int N){
    int n = blockIdx.x*256 + threadIdx.x;
    if (n >= N) return;
    float px = pos[3*n+0], py = pos[3*n+1], pz = pos[3*n+2];
    float f0x = floorf(px), f0y = floorf(py), f0z = floorf(pz);
    int ix = ((int)f0x)&127, iy = ((int)f0y)&127, iz = ((int)f0z)&127;
    float dx = px-f0x, dy = py-f0y, dz = pz-f0z;
    float wx[2]={1.f-dx,dx}, wy[2]={1.f-dy,dy}, wz[2]={1.f-dz,dz};
    int xi[2]={ix,(ix+1)&127}, yi[2]={iy,(iy+1)&127}, zi[2]={iz,(iz+1)&127};
    float fx=0.f, fy=0.f, fzv=0.f;
#pragma unroll
    for(int a=0;a<2;a++)
#pragma unroll
    for(int b=0;b<2;b++)
#pragma unroll
    for(int c=0;c<2;c++){
        float4 v4 = G[xi[a]*M2 + yi[b]*MESHN + zi[c]];
        float w = wx[a]*wy[b]*wz[c];
        fx += w*v4.x; fy += w*v4.y; fzv += w*v4.z;
    }
    float sc = 0.2f / drift[0];
    out[3*n+0]=px; out[3*n+1]=py; out[3*n+2]=pz;
    float* ov = out + (size_t)3*N;
    ov[3*n+0]=vel[3*n+0]+fx*sc;
    ov[3*n+1]=vel[3*n+1]+fy*sc;
    ov[3*n+2]=vel[3*n+2]+fzv*sc;
}

// ---------------------------------------------------------------------------
extern "C" void kernel_launch(void* const* d_in, const int* in_sizes, int n_in,
                              void* d_out, int out_size){
    const float* pos   = (const float*)d_in[0];
    const float* vel   = (const float*)d_in[1];
    const float* drift = (const float*)d_in[2];
    float* out = (float*)d_out;
    int N = in_sizes[0] / 3;

    void *pR,*pA,*pB,*pC,*pG;
    cudaGetSymbolAddress(&pR, g_real);
    cudaGetSymbolAddress(&pA, g_A);
    cudaGetSymbolAddress(&pB, g_B);
    cudaGetSymbolAddress(&pC, g_C);
    cudaGetSymbolAddress(&pG, g_G);
    float*  R = (float*)pR;
    float2* A = (float2*)pA;
    float2* B = (float2*)pB;
    float2* C = (float2*)pC;
    float4* G = (float4*)pG;

    cudaFuncSetAttribute(fft_plane_fwd, cudaFuncAttributeMaxDynamicSharedMemorySize, SMEM_PLANE);
    cudaFuncSetAttribute(fft_plane_inv, cudaFuncAttributeMaxDynamicSharedMemorySize, SMEM_PLANE);

    // 1. zero + CIC paint
    zero_kernel<<<M3/1024, 256>>>((float4*)R);
    paint_kernel<<<(N+255)/256, 256>>>(pos, R, N);

    // 2. forward z+y (per-x plane, y-phase pruned to |m_kz|<=41): R -> B
    fft_plane_fwd<<<128, 1024, SMEM_PLANE>>>(R, B);

    // 3. fused x (ball blocks only): fwd + filter + x-inv(Fxy)->A, x-inv(Fz)->C
    fft_x_fused<<<1024, 256>>>(B, A, C);

    // 4. inverse y+z planes (kz-rows pruned) -> G (float4, coalesced)
    fft_plane_inv<<<128, 1024, SMEM_PLANE>>>(A, C, G);

    // 5. CIC gather + velocity boost
    gather_kernel<<<(N+255)/256, 256>>>(pos, vel, drift, G, out, N);
}